// round 7
// baseline (speedup 1.0000x reference)
#include <cuda_runtime.h>

// ---------------------------------------------------------------------------
// Fully fused single-launch kernel. Algebraic collapse of the reference:
//   beta[b,s,h] = dot(S[b,s,h*64:(h+1)*64], W[b,h,:]) + c[b,h]
//   out[b,s,h*64+e] = RV[b,h,e] * beta * (S_mas[b,s] != 0)
// with W[b,h,d] = sum_e WQ_w[e,d]*R_K[b,h,e],  c = sum_e WQ_b[e]*R_K[b,h,e],
//      R_K = WK_w r + WK_b,  RV = WV_w r + WV_b,  r = R[b,h*64:...].
// Every block computes its batch's W/RV/c in a prologue (redundant across the
// 32 blocks per batch, but ~6us of chip-wide FMA hidden under an 80us
// DRAM-bound stream), then streams S -> out. One launch, no __device__ state.
// ---------------------------------------------------------------------------

template <int ROWS_PER_BLOCK, int UNROLL>
__global__ __launch_bounds__(256, 8) void fused_kernel(
    const float* __restrict__ S,
    const float* __restrict__ R,
    const int*   __restrict__ S_mas,
    const float* __restrict__ WQ_w, const float* __restrict__ WQ_b,
    const float* __restrict__ WK_w, const float* __restrict__ WK_b,
    const float* __restrict__ WV_w, const float* __restrict__ WV_b,
    float*       __restrict__ out,  int seq) {
    const int b  = blockIdx.x;
    const int t  = threadIdx.x;   // 0..255
    const int e  = t & 63;
    const int hq = t >> 6;        // 0..3, warp-uniform

    // 64 rows x 68 floats: 272B row stride (16B-aligned), bank-conflict-free
    // for both the coalesced stage writes and the per-lane row LDS.128 reads.
    __shared__ float WS[64 * 68];     // 17.4 KB weight tile (WK then WV)
    __shared__ float rk_s[1024];      // R_K, later reused as W
    __shared__ float rv_s[1024];      // R_V
    __shared__ float c_s[16];

    const float* Rb = R + b * 1024;

    // ---- Stage WK (coalesced), compute R_K[h,e] for h = hq, hq+4, hq+8, hq+12
#pragma unroll
    for (int i = 0; i < 16; i++) {
        const int idx = i * 256 + t;
        WS[(idx >> 6) * 68 + (idx & 63)] = WK_w[idx];
    }
    __syncthreads();

    float rk[4];
#pragma unroll
    for (int i = 0; i < 4; i++) rk[i] = WK_b[e];
    {
        const float4* wrow = reinterpret_cast<const float4*>(WS + e * 68);
#pragma unroll
        for (int j = 0; j < 16; j++) {
            const float4 w4 = wrow[j];              // LDS.128, conflict-free
#pragma unroll
            for (int i = 0; i < 4; i++) {
                const int h = i * 4 + hq;           // warp-uniform
                const float4 r4 =                   // uniform-address LDG
                    reinterpret_cast<const float4*>(Rb + h * 64)[j];
                rk[i] = fmaf(w4.x, r4.x, rk[i]);
                rk[i] = fmaf(w4.y, r4.y, rk[i]);
                rk[i] = fmaf(w4.z, r4.z, rk[i]);
                rk[i] = fmaf(w4.w, r4.w, rk[i]);
            }
        }
    }
    __syncthreads();    // all WK reads done before re-staging

    // ---- Stage WV over the same tile, compute R_V ----
#pragma unroll
    for (int i = 0; i < 16; i++) {
        const int idx = i * 256 + t;
        WS[(idx >> 6) * 68 + (idx & 63)] = WV_w[idx];
    }
    __syncthreads();

    float rv[4];
#pragma unroll
    for (int i = 0; i < 4; i++) rv[i] = WV_b[e];
    {
        const float4* wrow = reinterpret_cast<const float4*>(WS + e * 68);
#pragma unroll
        for (int j = 0; j < 16; j++) {
            const float4 w4 = wrow[j];
#pragma unroll
            for (int i = 0; i < 4; i++) {
                const int h = i * 4 + hq;
                const float4 r4 =
                    reinterpret_cast<const float4*>(Rb + h * 64)[j];
                rv[i] = fmaf(w4.x, r4.x, rv[i]);
                rv[i] = fmaf(w4.y, r4.y, rv[i]);
                rv[i] = fmaf(w4.z, r4.z, rv[i]);
                rv[i] = fmaf(w4.w, r4.w, rv[i]);
            }
        }
    }
#pragma unroll
    for (int i = 0; i < 4; i++) {
        const int h = i * 4 + hq;
        rk_s[h * 64 + e] = rk[i];
        rv_s[h * 64 + e] = rv[i];
    }
    __syncthreads();

    // ---- W[h,d] = sum_e2 WQ_w[e2,d] * R_K[h,e2]   (d = e, coalesced LDG) ----
    float w[4] = {0.f, 0.f, 0.f, 0.f};
#pragma unroll 8
    for (int e2 = 0; e2 < 64; e2++) {
        const float wq = WQ_w[e2 * 64 + e];        // 128B/warp, L2-hot
#pragma unroll
        for (int i = 0; i < 4; i++)
            w[i] = fmaf(wq, rk_s[(i * 4 + hq) * 64 + e2], w[i]);
    }
    if (t < 16) {
        float c = 0.f;
#pragma unroll 8
        for (int e2 = 0; e2 < 64; e2++)
            c = fmaf(WQ_b[e2], rk_s[t * 64 + e2], c);
        c_s[t] = c;
    }
    __syncthreads();    // all rk_s reads done
#pragma unroll
    for (int i = 0; i < 4; i++)
        rk_s[(i * 4 + hq) * 64 + e] = w[i];        // rk_s is now W
    __syncthreads();

    // ---- Per-thread stream constants (same mapping as before) ----
    const float4 w4  = reinterpret_cast<const float4*>(rk_s)[t];
    const float4 rv4 = reinterpret_cast<const float4*>(rv_s)[t];
    const float  c   = c_s[t >> 4];

    // ---- Streaming pass ----
    const int row0 = blockIdx.y * ROWS_PER_BLOCK;
    const float4* Sp = reinterpret_cast<const float4*>(S) + (size_t)b * seq * 256;
    float4*       Op = reinterpret_cast<float4*>(out)     + (size_t)b * seq * 256;
    const int*    mp = S_mas + (size_t)b * seq;

    const int row_end = (row0 + ROWS_PER_BLOCK < seq) ? row0 + ROWS_PER_BLOCK : seq;

    int r = row0;
    for (; r + UNROLL <= row_end; r += UNROLL) {
        float4 s[UNROLL];
        int    m[UNROLL];
#pragma unroll
        for (int u = 0; u < UNROLL; u++) {
            s[u] = Sp[(size_t)(r + u) * 256 + t];
            m[u] = mp[r + u];
        }
#pragma unroll
        for (int u = 0; u < UNROLL; u++) {
            float p = s[u].x * w4.x + s[u].y * w4.y + s[u].z * w4.z + s[u].w * w4.w;
            p += __shfl_xor_sync(0xffffffffu, p, 8, 16);
            p += __shfl_xor_sync(0xffffffffu, p, 4, 16);
            p += __shfl_xor_sync(0xffffffffu, p, 2, 16);
            p += __shfl_xor_sync(0xffffffffu, p, 1, 16);
            const float beta = (p + c) * (m[u] != 0 ? 1.0f : 0.0f);
            float4 o;
            o.x = rv4.x * beta;
            o.y = rv4.y * beta;
            o.z = rv4.z * beta;
            o.w = rv4.w * beta;
            Op[(size_t)(r + u) * 256 + t] = o;
        }
    }
    for (; r < row_end; r++) {
        float4 s = Sp[(size_t)r * 256 + t];
        int    m = mp[r];
        float p = s.x * w4.x + s.y * w4.y + s.z * w4.z + s.w * w4.w;
        p += __shfl_xor_sync(0xffffffffu, p, 8, 16);
        p += __shfl_xor_sync(0xffffffffu, p, 4, 16);
        p += __shfl_xor_sync(0xffffffffu, p, 2, 16);
        p += __shfl_xor_sync(0xffffffffu, p, 1, 16);
        const float beta = (p + c) * (m != 0 ? 1.0f : 0.0f);
        float4 o;
        o.x = rv4.x * beta;
        o.y = rv4.y * beta;
        o.z = rv4.z * beta;
        o.w = rv4.w * beta;
        Op[(size_t)r * 256 + t] = o;
    }
}

// ---------------------------------------------------------------------------
// Launch. Inputs (metadata order):
//   0 S (dps,seq,1024) f32   1 R (dps,1,1024) f32
//   2 S_mas (dps,seq,1) i32  3 R_mas (dps,1,1) i32 (dead)
//   4 WQ_w  5 WQ_b  6 WK_w  7 WK_b  8 WV_w  9 WV_b
// ---------------------------------------------------------------------------
extern "C" void kernel_launch(void* const* d_in, const int* in_sizes, int n_in,
                              void* d_out, int out_size) {
    const float* S     = (const float*)d_in[0];
    const float* R     = (const float*)d_in[1];
    const int*   S_mas = (const int*)  d_in[2];
    const float* WQ_w  = (const float*)d_in[4];
    const float* WQ_b  = (const float*)d_in[5];
    const float* WK_w  = (const float*)d_in[6];
    const float* WK_b  = (const float*)d_in[7];
    const float* WV_w  = (const float*)d_in[8];
    const float* WV_b  = (const float*)d_in[9];
    float* out = (float*)d_out;

    int dps = in_sizes[1] / 1024;          // R element count = dps*1024
    int seq = in_sizes[0] / (dps * 1024);  // S element count = dps*seq*1024

    constexpr int ROWS   = 64;
    constexpr int UNROLL = 4;
    int nblk = (seq + ROWS - 1) / ROWS;
    fused_kernel<ROWS, UNROLL><<<dim3(dps, nblk), 256>>>(
        S, R, S_mas, WQ_w, WQ_b, WK_w, WK_b, WV_w, WV_b, out, seq);
}

// round 8
// speedup vs baseline: 1.0954x; 1.0954x over previous
#include <cuda_runtime.h>

// ---------------------------------------------------------------------------
// Single-launch fused kernel, v2 (low register/smem pressure prologue).
// Algebraic collapse of the reference:
//   beta[b,s,h] = dot(S[b,s,h*64:(h+1)*64], W[b,h,:]) + c[b,h]
//   out[b,s,h*64+e] = RV[b,h,e] * beta * (S_mas[b,s] != 0)
// with W[b,h,d] = sum_e WQ_w[e,d]*R_K[b,h,e],  c = sum_e WQ_b[e]*R_K[b,h,e],
//      R_K = WK_w r + WK_b,  RV = WV_w r + WV_b,  r = R[b, h*64:(h+1)*64].
//
// Prologue: thread t (head h = t>>4, elems e0 = (t&15)*4) computes ONLY its
// own 4-wide slice of RV and W (plus c), sharing R_K across the head's 16
// lanes through a 4KB smem buffer. ~832 FMA + ~110 L2-hot LDG.128 per
// thread, one __syncthreads, no weight smem tile -> no spills, L1 intact.
// Then the unchanged HBM-bound streaming loop (79.5us standalone).
// ---------------------------------------------------------------------------

template <int ROWS_PER_BLOCK, int UNROLL>
__global__ __launch_bounds__(256) void fused_kernel(
    const float* __restrict__ S,
    const float* __restrict__ R,
    const int*   __restrict__ S_mas,
    const float* __restrict__ WQ_w, const float* __restrict__ WQ_b,
    const float* __restrict__ WK_w, const float* __restrict__ WK_b,
    const float* __restrict__ WV_w, const float* __restrict__ WV_b,
    float*       __restrict__ out,  int seq) {
    const int b  = blockIdx.x;
    const int t  = threadIdx.x;   // 0..255
    const int h  = t >> 4;        // head, 16 consecutive lanes
    const int e0 = (t & 15) * 4;  // this thread's 4 elements / dims

    __shared__ float rk_s[1024];  // R_K[h, e], 4 KB

    // ---- Phase 1: rk[i], rv[i] for e = e0+i ----
    const float4* r4p  = reinterpret_cast<const float4*>(R + b * 1024 + h * 64);
    const float4* wkb  = reinterpret_cast<const float4*>(WK_w);
    const float4* wvb  = reinterpret_cast<const float4*>(WV_w);
    const float4  kb4  = reinterpret_cast<const float4*>(WK_b)[t & 15];
    const float4  vb4  = reinterpret_cast<const float4*>(WV_b)[t & 15];

    float rk[4] = {kb4.x, kb4.y, kb4.z, kb4.w};
    float rv[4] = {vb4.x, vb4.y, vb4.z, vb4.w};
#pragma unroll 4
    for (int j = 0; j < 16; j++) {
        const float4 r4 = r4p[j];   // broadcast within 16-lane group
#pragma unroll
        for (int i = 0; i < 4; i++) {
            const float4 k4 = wkb[(e0 + i) * 16 + j];   // row (e0+i), chunk j
            rk[i] = fmaf(k4.x, r4.x, rk[i]);
            rk[i] = fmaf(k4.y, r4.y, rk[i]);
            rk[i] = fmaf(k4.z, r4.z, rk[i]);
            rk[i] = fmaf(k4.w, r4.w, rk[i]);
        }
#pragma unroll
        for (int i = 0; i < 4; i++) {
            const float4 v4 = wvb[(e0 + i) * 16 + j];
            rv[i] = fmaf(v4.x, r4.x, rv[i]);
            rv[i] = fmaf(v4.y, r4.y, rv[i]);
            rv[i] = fmaf(v4.z, r4.z, rv[i]);
            rv[i] = fmaf(v4.w, r4.w, rv[i]);
        }
    }
#pragma unroll
    for (int i = 0; i < 4; i++) rk_s[h * 64 + e0 + i] = rk[i];
    __syncthreads();

    // ---- Phase 2: w[i] = W[h, e0+i] and c[h] ----
    // One LDG.128 per e2 gives the 4 d-values this thread owns; coalesced
    // across the 16-lane group. rk_s read is a broadcast. c folded in.
    float w[4] = {0.f, 0.f, 0.f, 0.f};
    float c    = 0.f;
#pragma unroll 8
    for (int e2 = 0; e2 < 64; e2++) {
        const float  rke = rk_s[h * 64 + e2];
        const float4 q4  = reinterpret_cast<const float4*>(WQ_w + e2 * 64)[t & 15];
        w[0] = fmaf(q4.x, rke, w[0]);
        w[1] = fmaf(q4.y, rke, w[1]);
        w[2] = fmaf(q4.z, rke, w[2]);
        w[3] = fmaf(q4.w, rke, w[3]);
        c    = fmaf(WQ_b[e2], rke, c);
    }

    const float4 w4  = make_float4(w[0], w[1], w[2], w[3]);
    const float4 rv4 = make_float4(rv[0], rv[1], rv[2], rv[3]);

    // ---- Streaming pass (unchanged hot loop) ----
    const int row0 = blockIdx.y * ROWS_PER_BLOCK;
    const float4* Sp = reinterpret_cast<const float4*>(S) + (size_t)b * seq * 256;
    float4*       Op = reinterpret_cast<float4*>(out)     + (size_t)b * seq * 256;
    const int*    mp = S_mas + (size_t)b * seq;

    const int row_end = (row0 + ROWS_PER_BLOCK < seq) ? row0 + ROWS_PER_BLOCK : seq;

    int r = row0;
    for (; r + UNROLL <= row_end; r += UNROLL) {
        float4 s[UNROLL];
        int    m[UNROLL];
#pragma unroll
        for (int u = 0; u < UNROLL; u++) {
            s[u] = Sp[(size_t)(r + u) * 256 + t];
            m[u] = mp[r + u];
        }
#pragma unroll
        for (int u = 0; u < UNROLL; u++) {
            float p = s[u].x * w4.x + s[u].y * w4.y + s[u].z * w4.z + s[u].w * w4.w;
            p += __shfl_xor_sync(0xffffffffu, p, 8, 16);
            p += __shfl_xor_sync(0xffffffffu, p, 4, 16);
            p += __shfl_xor_sync(0xffffffffu, p, 2, 16);
            p += __shfl_xor_sync(0xffffffffu, p, 1, 16);
            const float beta = (p + c) * (m[u] != 0 ? 1.0f : 0.0f);
            float4 o;
            o.x = rv4.x * beta;
            o.y = rv4.y * beta;
            o.z = rv4.z * beta;
            o.w = rv4.w * beta;
            Op[(size_t)(r + u) * 256 + t] = o;
        }
    }
    for (; r < row_end; r++) {
        float4 s = Sp[(size_t)r * 256 + t];
        int    m = mp[r];
        float p = s.x * w4.x + s.y * w4.y + s.z * w4.z + s.w * w4.w;
        p += __shfl_xor_sync(0xffffffffu, p, 8, 16);
        p += __shfl_xor_sync(0xffffffffu, p, 4, 16);
        p += __shfl_xor_sync(0xffffffffu, p, 2, 16);
        p += __shfl_xor_sync(0xffffffffu, p, 1, 16);
        const float beta = (p + c) * (m != 0 ? 1.0f : 0.0f);
        float4 o;
        o.x = rv4.x * beta;
        o.y = rv4.y * beta;
        o.z = rv4.z * beta;
        o.w = rv4.w * beta;
        Op[(size_t)r * 256 + t] = o;
    }
}

// ---------------------------------------------------------------------------
// Launch. Inputs (metadata order):
//   0 S (dps,seq,1024) f32   1 R (dps,1,1024) f32
//   2 S_mas (dps,seq,1) i32  3 R_mas (dps,1,1) i32 (dead)
//   4 WQ_w  5 WQ_b  6 WK_w  7 WK_b  8 WV_w  9 WV_b
// ---------------------------------------------------------------------------
extern "C" void kernel_launch(void* const* d_in, const int* in_sizes, int n_in,
                              void* d_out, int out_size) {
    const float* S     = (const float*)d_in[0];
    const float* R     = (const float*)d_in[1];
    const int*   S_mas = (const int*)  d_in[2];
    const float* WQ_w  = (const float*)d_in[4];
    const float* WQ_b  = (const float*)d_in[5];
    const float* WK_w  = (const float*)d_in[6];
    const float* WK_b  = (const float*)d_in[7];
    const float* WV_w  = (const float*)d_in[8];
    const float* WV_b  = (const float*)d_in[9];
    float* out = (float*)d_out;

    int dps = in_sizes[1] / 1024;          // R element count = dps*1024
    int seq = in_sizes[0] / (dps * 1024);  // S element count = dps*seq*1024

    constexpr int ROWS   = 64;
    constexpr int UNROLL = 4;
    int nblk = (seq + ROWS - 1) / ROWS;
    fused_kernel<ROWS, UNROLL><<<dim3(dps, nblk), 256>>>(
        S, R, S_mas, WQ_w, WQ_b, WK_w, WK_b, WV_w, WV_b, out, seq);
}

// round 9
// speedup vs baseline: 1.7847x; 1.6293x over previous
#include <cuda_runtime.h>

// ---------------------------------------------------------------------------
// Single-launch fused kernel, v3. Algebraic collapse of the reference:
//   beta[b,s,h] = dot(S[b,s,h*64:(h+1)*64], W[b,h,:]) + c[b,h]
//   out[b,s,h*64+e] = RV[b,h,e] * beta * (S_mas[b,s] != 0)
// with W[b,h,d] = sum_e WQ_w[e,d]*R_K[b,h,e],  c = sum_e WQ_b[e]*R_K[b,h,e],
//      R_K = WK_w r + WK_b,  RV = WV_w r + WV_b,  r = R[b, h*64:(h+1)*64].
//
// Prologue (per block, redundant across the 16 blocks/batch):
//  - WK/WV staged sequentially through ONE transposed smem tile WT[d*68+e]
//    (coalesced LDG stage; conflict-free LDS.128 reads, upper half-warp
//    broadcasts). R staged in smem. WQ phase reads global columns coalesced.
//  - thread t -> (h = t>>4, e-quad e0 = (t&15)*4) computes only its own
//    rk/rv/w quads; R_K shared across the head via 4KB rk_s.
//  ~7us chip-wide at 512 blocks, conflict/coalesce-clean -> no L1 blowup.
// Then the unchanged HBM-bound streaming loop.
// ---------------------------------------------------------------------------

template <int ROWS_PER_BLOCK, int UNROLL>
__global__ __launch_bounds__(256) void fused_kernel(
    const float* __restrict__ S,
    const float* __restrict__ R,
    const int*   __restrict__ S_mas,
    const float* __restrict__ WQ_w, const float* __restrict__ WQ_b,
    const float* __restrict__ WK_w, const float* __restrict__ WK_b,
    const float* __restrict__ WV_w, const float* __restrict__ WV_b,
    float*       __restrict__ out,  int seq) {
    const int b  = blockIdx.x;
    const int t  = threadIdx.x;   // 0..255
    const int h  = t >> 4;        // head, 16 consecutive lanes
    const int q  = t & 15;
    const int e0 = q * 4;         // this thread's 4 elements / dims

    __shared__ float WT[64 * 68];   // transposed weight tile, 17.4 KB
    __shared__ float r_s[1024];     // R row, 4 KB
    __shared__ float rk_s[1024];    // R_K[h,e], 4 KB

    // ---- Stage R (coalesced) and WK transposed: WT[d*68+e] = WK_w[e*64+d]
#pragma unroll
    for (int i = 0; i < 4; i++)
        r_s[i * 256 + t] = R[b * 1024 + i * 256 + t];
#pragma unroll
    for (int i = 0; i < 16; i++) {
        const int idx = i * 256 + t;             // e = idx>>6, d = idx&63
        WT[(idx & 63) * 68 + (idx >> 6)] = WK_w[idx];
    }
    __syncthreads();

    // ---- rk quad: rk[i] = WK_b[e0+i] + sum_d WT[d][e0+i] * r[h*64+d] ----
    float4 rkq;
    {
        const float4 kb = reinterpret_cast<const float4*>(WK_b)[q];
        float a0 = kb.x, a1 = kb.y, a2 = kb.z, a3 = kb.w;
        const float4* rr = reinterpret_cast<const float4*>(r_s + h * 64);
#pragma unroll
        for (int j = 0; j < 16; j++) {
            const float4 r4 = rr[j];             // broadcast LDS.128
            const float* base = WT + (4 * j) * 68 + e0;
            const float4 w0 = *reinterpret_cast<const float4*>(base);
            const float4 w1 = *reinterpret_cast<const float4*>(base + 68);
            const float4 w2 = *reinterpret_cast<const float4*>(base + 136);
            const float4 w3 = *reinterpret_cast<const float4*>(base + 204);
            a0 = fmaf(w0.x, r4.x, a0); a1 = fmaf(w0.y, r4.x, a1);
            a2 = fmaf(w0.z, r4.x, a2); a3 = fmaf(w0.w, r4.x, a3);
            a0 = fmaf(w1.x, r4.y, a0); a1 = fmaf(w1.y, r4.y, a1);
            a2 = fmaf(w1.z, r4.y, a2); a3 = fmaf(w1.w, r4.y, a3);
            a0 = fmaf(w2.x, r4.z, a0); a1 = fmaf(w2.y, r4.z, a1);
            a2 = fmaf(w2.z, r4.z, a2); a3 = fmaf(w2.w, r4.z, a3);
            a0 = fmaf(w3.x, r4.w, a0); a1 = fmaf(w3.y, r4.w, a1);
            a2 = fmaf(w3.z, r4.w, a2); a3 = fmaf(w3.w, r4.w, a3);
        }
        rkq = make_float4(a0, a1, a2, a3);
    }
    reinterpret_cast<float4*>(rk_s)[t] = rkq;    // rk_s[h*64+e0..+3]
    __syncthreads();                             // WT reads done; rk_s ready

    // ---- Restage WT with WV, compute rv quad ----
#pragma unroll
    for (int i = 0; i < 16; i++) {
        const int idx = i * 256 + t;
        WT[(idx & 63) * 68 + (idx >> 6)] = WV_w[idx];
    }
    __syncthreads();

    float4 rv4;
    {
        const float4 vb = reinterpret_cast<const float4*>(WV_b)[q];
        float a0 = vb.x, a1 = vb.y, a2 = vb.z, a3 = vb.w;
        const float4* rr = reinterpret_cast<const float4*>(r_s + h * 64);
#pragma unroll
        for (int j = 0; j < 16; j++) {
            const float4 r4 = rr[j];
            const float* base = WT + (4 * j) * 68 + e0;
            const float4 w0 = *reinterpret_cast<const float4*>(base);
            const float4 w1 = *reinterpret_cast<const float4*>(base + 68);
            const float4 w2 = *reinterpret_cast<const float4*>(base + 136);
            const float4 w3 = *reinterpret_cast<const float4*>(base + 204);
            a0 = fmaf(w0.x, r4.x, a0); a1 = fmaf(w0.y, r4.x, a1);
            a2 = fmaf(w0.z, r4.x, a2); a3 = fmaf(w0.w, r4.x, a3);
            a0 = fmaf(w1.x, r4.y, a0); a1 = fmaf(w1.y, r4.y, a1);
            a2 = fmaf(w1.z, r4.y, a2); a3 = fmaf(w1.w, r4.y, a3);
            a0 = fmaf(w2.x, r4.z, a0); a1 = fmaf(w2.y, r4.z, a1);
            a2 = fmaf(w2.z, r4.z, a2); a3 = fmaf(w2.w, r4.z, a3);
            a0 = fmaf(w3.x, r4.w, a0); a1 = fmaf(w3.y, r4.w, a1);
            a2 = fmaf(w3.z, r4.w, a2); a3 = fmaf(w3.w, r4.w, a3);
        }
        rv4 = make_float4(a0, a1, a2, a3);
    }

    // ---- w quad + c:  w[i] = sum_e2 WQ_w[e2, e0+i] * R_K[h,e2] ----
    // WQ_w read is coalesced per 16-lane group (256B), broadcast across
    // half-warps; rk_s read is a broadcast; WQ_b uniform (L1-hot).
    float w0 = 0.f, w1 = 0.f, w2 = 0.f, w3 = 0.f, c = 0.f;
#pragma unroll 8
    for (int e2 = 0; e2 < 64; e2++) {
        const float  rke = rk_s[h * 64 + e2];
        const float4 q4  = reinterpret_cast<const float4*>(WQ_w + e2 * 64)[q];
        w0 = fmaf(q4.x, rke, w0);
        w1 = fmaf(q4.y, rke, w1);
        w2 = fmaf(q4.z, rke, w2);
        w3 = fmaf(q4.w, rke, w3);
        c  = fmaf(WQ_b[e2], rke, c);
    }
    const float4 w4 = make_float4(w0, w1, w2, w3);

    // ---- Streaming pass (unchanged hot loop) ----
    const int row0 = blockIdx.y * ROWS_PER_BLOCK;
    const float4* Sp = reinterpret_cast<const float4*>(S) + (size_t)b * seq * 256;
    float4*       Op = reinterpret_cast<float4*>(out)     + (size_t)b * seq * 256;
    const int*    mp = S_mas + (size_t)b * seq;

    const int row_end = (row0 + ROWS_PER_BLOCK < seq) ? row0 + ROWS_PER_BLOCK : seq;

    int r = row0;
    for (; r + UNROLL <= row_end; r += UNROLL) {
        float4 s[UNROLL];
        int    m[UNROLL];
#pragma unroll
        for (int u = 0; u < UNROLL; u++) {
            s[u] = Sp[(size_t)(r + u) * 256 + t];
            m[u] = mp[r + u];
        }
#pragma unroll
        for (int u = 0; u < UNROLL; u++) {
            float p = s[u].x * w4.x + s[u].y * w4.y + s[u].z * w4.z + s[u].w * w4.w;
            p += __shfl_xor_sync(0xffffffffu, p, 8, 16);
            p += __shfl_xor_sync(0xffffffffu, p, 4, 16);
            p += __shfl_xor_sync(0xffffffffu, p, 2, 16);
            p += __shfl_xor_sync(0xffffffffu, p, 1, 16);
            const float beta = (p + c) * (m[u] != 0 ? 1.0f : 0.0f);
            float4 o;
            o.x = rv4.x * beta;
            o.y = rv4.y * beta;
            o.z = rv4.z * beta;
            o.w = rv4.w * beta;
            Op[(size_t)(r + u) * 256 + t] = o;
        }
    }
    for (; r < row_end; r++) {
        float4 s = Sp[(size_t)r * 256 + t];
        int    m = mp[r];
        float p = s.x * w4.x + s.y * w4.y + s.z * w4.z + s.w * w4.w;
        p += __shfl_xor_sync(0xffffffffu, p, 8, 16);
        p += __shfl_xor_sync(0xffffffffu, p, 4, 16);
        p += __shfl_xor_sync(0xffffffffu, p, 2, 16);
        p += __shfl_xor_sync(0xffffffffu, p, 1, 16);
        const float beta = (p + c) * (m != 0 ? 1.0f : 0.0f);
        float4 o;
        o.x = rv4.x * beta;
        o.y = rv4.y * beta;
        o.z = rv4.z * beta;
        o.w = rv4.w * beta;
        Op[(size_t)r * 256 + t] = o;
    }
}

// ---------------------------------------------------------------------------
// Launch. Inputs (metadata order):
//   0 S (dps,seq,1024) f32   1 R (dps,1,1024) f32
//   2 S_mas (dps,seq,1) i32  3 R_mas (dps,1,1) i32 (dead)
//   4 WQ_w  5 WQ_b  6 WK_w  7 WK_b  8 WV_w  9 WV_b
// ---------------------------------------------------------------------------
extern "C" void kernel_launch(void* const* d_in, const int* in_sizes, int n_in,
                              void* d_out, int out_size) {
    const float* S     = (const float*)d_in[0];
    const float* R     = (const float*)d_in[1];
    const int*   S_mas = (const int*)  d_in[2];
    const float* WQ_w  = (const float*)d_in[4];
    const float* WQ_b  = (const float*)d_in[5];
    const float* WK_w  = (const float*)d_in[6];
    const float* WK_b  = (const float*)d_in[7];
    const float* WV_w  = (const float*)d_in[8];
    const float* WV_b  = (const float*)d_in[9];
    float* out = (float*)d_out;

    int dps = in_sizes[1] / 1024;          // R element count = dps*1024
    int seq = in_sizes[0] / (dps * 1024);  // S element count = dps*seq*1024

    constexpr int ROWS   = 128;            // 512 blocks: halves prologue cost
    constexpr int UNROLL = 4;
    int nblk = (seq + ROWS - 1) / ROWS;
    fused_kernel<ROWS, UNROLL><<<dim3(dps, nblk), 256>>>(
        S, R, S_mas, WQ_w, WQ_b, WK_w, WK_b, WV_w, WV_b, out, seq);
}

// round 10
// speedup vs baseline: 1.8061x; 1.0120x over previous
#include <cuda_runtime.h>

// ---------------------------------------------------------------------------
// Algebraic collapse of the reference:
//   beta[b,s,h] = dot(S[b,s,h*64:(h+1)*64], W[b,h,:]) + c[b,h]
//   out[b,s,h*64+e] = RV[b,h,e] * beta * (S_mas[b,s] != 0)
// with W[b,h,d] = sum_e WQ_w[e,d]*R_K[b,h,e],  c = sum_e WQ_b[e]*R_K[b,h,e],
//      R_K = WK_w r + WK_b,  RV = WV_w r + WV_b,  r = R[b, h*64:(h+1)*64].
//
// Kernel 1 (grid=dps, 256 thr): coalesce/conflict-clean precompute via a
// transposed smem weight tile (the R8 prologue, now x32 redundancy only).
// Kernel 2: the proven 79.5us HBM-bound streaming pass (77.5% DRAM).
// ---------------------------------------------------------------------------

#define MAX_DPS 64

__device__ float g_W [MAX_DPS * 1024];
__device__ float g_RV[MAX_DPS * 1024];
__device__ float g_C [MAX_DPS * 16];

// ---------------------------------------------------------------------------
// Kernel 1: per-batch precompute. grid (dps), block 256.
// thread t -> (h = t>>4, e-quad e0 = (t&15)*4). WK/WV staged sequentially
// through ONE transposed tile WT[d*68+e]: staging LDG is coalesced, compute
// reads are conflict-free LDS.128 (16 lanes cover one row; half-warp
// broadcast). WQ phase reads global columns coalesced (256B per 16 lanes).
// ---------------------------------------------------------------------------
__global__ __launch_bounds__(256) void precompute_kernel(
    const float* __restrict__ R,
    const float* __restrict__ WQ_w, const float* __restrict__ WQ_b,
    const float* __restrict__ WK_w, const float* __restrict__ WK_b,
    const float* __restrict__ WV_w, const float* __restrict__ WV_b) {
    const int b  = blockIdx.x;
    const int t  = threadIdx.x;   // 0..255
    const int h  = t >> 4;        // head, 16 consecutive lanes
    const int q  = t & 15;
    const int e0 = q * 4;

    __shared__ float WT[64 * 68];   // transposed weight tile, 17.4 KB
    __shared__ float r_s[1024];
    __shared__ float rk_s[1024];

    // Stage R (coalesced) and WK transposed: WT[d*68+e] = WK_w[e*64+d]
#pragma unroll
    for (int i = 0; i < 4; i++)
        r_s[i * 256 + t] = R[b * 1024 + i * 256 + t];
#pragma unroll
    for (int i = 0; i < 16; i++) {
        const int idx = i * 256 + t;             // e = idx>>6, d = idx&63
        WT[(idx & 63) * 68 + (idx >> 6)] = WK_w[idx];
    }
    __syncthreads();

    // rk quad: rk[i] = WK_b[e0+i] + sum_d WT[d][e0+i] * r[h*64+d]
    float4 rkq;
    {
        const float4 kb = reinterpret_cast<const float4*>(WK_b)[q];
        float a0 = kb.x, a1 = kb.y, a2 = kb.z, a3 = kb.w;
        const float4* rr = reinterpret_cast<const float4*>(r_s + h * 64);
#pragma unroll
        for (int j = 0; j < 16; j++) {
            const float4 r4 = rr[j];             // broadcast LDS.128
            const float* base = WT + (4 * j) * 68 + e0;
            const float4 w0 = *reinterpret_cast<const float4*>(base);
            const float4 w1 = *reinterpret_cast<const float4*>(base + 68);
            const float4 w2 = *reinterpret_cast<const float4*>(base + 136);
            const float4 w3 = *reinterpret_cast<const float4*>(base + 204);
            a0 = fmaf(w0.x, r4.x, a0); a1 = fmaf(w0.y, r4.x, a1);
            a2 = fmaf(w0.z, r4.x, a2); a3 = fmaf(w0.w, r4.x, a3);
            a0 = fmaf(w1.x, r4.y, a0); a1 = fmaf(w1.y, r4.y, a1);
            a2 = fmaf(w1.z, r4.y, a2); a3 = fmaf(w1.w, r4.y, a3);
            a0 = fmaf(w2.x, r4.z, a0); a1 = fmaf(w2.y, r4.z, a1);
            a2 = fmaf(w2.z, r4.z, a2); a3 = fmaf(w2.w, r4.z, a3);
            a0 = fmaf(w3.x, r4.w, a0); a1 = fmaf(w3.y, r4.w, a1);
            a2 = fmaf(w3.z, r4.w, a2); a3 = fmaf(w3.w, r4.w, a3);
        }
        rkq = make_float4(a0, a1, a2, a3);
    }
    reinterpret_cast<float4*>(rk_s)[t] = rkq;
    __syncthreads();                             // WT reads done; rk_s ready

    // Restage WT with WV, compute rv quad, store to g_RV
#pragma unroll
    for (int i = 0; i < 16; i++) {
        const int idx = i * 256 + t;
        WT[(idx & 63) * 68 + (idx >> 6)] = WV_w[idx];
    }
    __syncthreads();
    {
        const float4 vb = reinterpret_cast<const float4*>(WV_b)[q];
        float a0 = vb.x, a1 = vb.y, a2 = vb.z, a3 = vb.w;
        const float4* rr = reinterpret_cast<const float4*>(r_s + h * 64);
#pragma unroll
        for (int j = 0; j < 16; j++) {
            const float4 r4 = rr[j];
            const float* base = WT + (4 * j) * 68 + e0;
            const float4 w0 = *reinterpret_cast<const float4*>(base);
            const float4 w1 = *reinterpret_cast<const float4*>(base + 68);
            const float4 w2 = *reinterpret_cast<const float4*>(base + 136);
            const float4 w3 = *reinterpret_cast<const float4*>(base + 204);
            a0 = fmaf(w0.x, r4.x, a0); a1 = fmaf(w0.y, r4.x, a1);
            a2 = fmaf(w0.z, r4.x, a2); a3 = fmaf(w0.w, r4.x, a3);
            a0 = fmaf(w1.x, r4.y, a0); a1 = fmaf(w1.y, r4.y, a1);
            a2 = fmaf(w1.z, r4.y, a2); a3 = fmaf(w1.w, r4.y, a3);
            a0 = fmaf(w2.x, r4.z, a0); a1 = fmaf(w2.y, r4.z, a1);
            a2 = fmaf(w2.z, r4.z, a2); a3 = fmaf(w2.w, r4.z, a3);
            a0 = fmaf(w3.x, r4.w, a0); a1 = fmaf(w3.y, r4.w, a1);
            a2 = fmaf(w3.z, r4.w, a2); a3 = fmaf(w3.w, r4.w, a3);
        }
        reinterpret_cast<float4*>(g_RV + b * 1024)[t] =
            make_float4(a0, a1, a2, a3);
    }

    // w quad + c: w[i] = sum_e2 WQ_w[e2, e0+i] * R_K[h,e2]
    float w0 = 0.f, w1 = 0.f, w2 = 0.f, w3 = 0.f, c = 0.f;
#pragma unroll 8
    for (int e2 = 0; e2 < 64; e2++) {
        const float  rke = rk_s[h * 64 + e2];
        const float4 q4  = reinterpret_cast<const float4*>(WQ_w + e2 * 64)[q];
        w0 = fmaf(q4.x, rke, w0);
        w1 = fmaf(q4.y, rke, w1);
        w2 = fmaf(q4.z, rke, w2);
        w3 = fmaf(q4.w, rke, w3);
        c  = fmaf(WQ_b[e2], rke, c);
    }
    reinterpret_cast<float4*>(g_W + b * 1024)[t] = make_float4(w0, w1, w2, w3);
    if (q == 0) g_C[b * 16 + h] = c;
}

// ---------------------------------------------------------------------------
// Kernel 2: streaming pass (proven 79.5us / 77.5% DRAM configuration).
// grid (dps, seq/ROWS), block 256. Thread owns one float4 of the row;
// head = 16 lanes; dot reduced with shfl.xor width=16.
// ---------------------------------------------------------------------------
template <int ROWS_PER_BLOCK, int UNROLL>
__global__ __launch_bounds__(256) void stream_kernel(
    const float* __restrict__ S,
    const int*   __restrict__ S_mas,
    float*       __restrict__ out,
    int seq) {
    const int b   = blockIdx.x;
    const int tid = threadIdx.x;      // 0..255
    const int h   = tid >> 4;         // head = 16 consecutive lanes

    const float4 w  = reinterpret_cast<const float4*>(g_W  + b * 1024)[tid];
    const float4 rv = reinterpret_cast<const float4*>(g_RV + b * 1024)[tid];
    const float  c  = g_C[b * 16 + h];

    const int row0 = blockIdx.y * ROWS_PER_BLOCK;
    const float4* Sp = reinterpret_cast<const float4*>(S) + (size_t)b * seq * 256;
    float4*       Op = reinterpret_cast<float4*>(out)     + (size_t)b * seq * 256;
    const int*    mp = S_mas + (size_t)b * seq;

    const int row_end = (row0 + ROWS_PER_BLOCK < seq) ? row0 + ROWS_PER_BLOCK : seq;

    int r = row0;
    for (; r + UNROLL <= row_end; r += UNROLL) {
        float4 s[UNROLL];
        int    m[UNROLL];
#pragma unroll
        for (int u = 0; u < UNROLL; u++) {
            s[u] = Sp[(size_t)(r + u) * 256 + tid];
            m[u] = mp[r + u];
        }
#pragma unroll
        for (int u = 0; u < UNROLL; u++) {
            float p = s[u].x * w.x + s[u].y * w.y + s[u].z * w.z + s[u].w * w.w;
            p += __shfl_xor_sync(0xffffffffu, p, 8, 16);
            p += __shfl_xor_sync(0xffffffffu, p, 4, 16);
            p += __shfl_xor_sync(0xffffffffu, p, 2, 16);
            p += __shfl_xor_sync(0xffffffffu, p, 1, 16);
            const float beta = (p + c) * (m[u] != 0 ? 1.0f : 0.0f);
            float4 o;
            o.x = rv.x * beta;
            o.y = rv.y * beta;
            o.z = rv.z * beta;
            o.w = rv.w * beta;
            Op[(size_t)(r + u) * 256 + tid] = o;
        }
    }
    for (; r < row_end; r++) {
        float4 s = Sp[(size_t)r * 256 + tid];
        int    m = mp[r];
        float p = s.x * w.x + s.y * w.y + s.z * w.z + s.w * w.w;
        p += __shfl_xor_sync(0xffffffffu, p, 8, 16);
        p += __shfl_xor_sync(0xffffffffu, p, 4, 16);
        p += __shfl_xor_sync(0xffffffffu, p, 2, 16);
        p += __shfl_xor_sync(0xffffffffu, p, 1, 16);
        const float beta = (p + c) * (m != 0 ? 1.0f : 0.0f);
        float4 o;
        o.x = rv.x * beta;
        o.y = rv.y * beta;
        o.z = rv.z * beta;
        o.w = rv.w * beta;
        Op[(size_t)r * 256 + tid] = o;
    }
}

// ---------------------------------------------------------------------------
// Launch. Inputs (metadata order):
//   0 S (dps,seq,1024) f32   1 R (dps,1,1024) f32
//   2 S_mas (dps,seq,1) i32  3 R_mas (dps,1,1) i32 (dead)
//   4 WQ_w  5 WQ_b  6 WK_w  7 WK_b  8 WV_w  9 WV_b
// ---------------------------------------------------------------------------
extern "C" void kernel_launch(void* const* d_in, const int* in_sizes, int n_in,
                              void* d_out, int out_size) {
    const float* S     = (const float*)d_in[0];
    const float* R     = (const float*)d_in[1];
    const int*   S_mas = (const int*)  d_in[2];
    const float* WQ_w  = (const float*)d_in[4];
    const float* WQ_b  = (const float*)d_in[5];
    const float* WK_w  = (const float*)d_in[6];
    const float* WK_b  = (const float*)d_in[7];
    const float* WV_w  = (const float*)d_in[8];
    const float* WV_b  = (const float*)d_in[9];
    float* out = (float*)d_out;

    int dps = in_sizes[1] / 1024;          // R element count = dps*1024
    if (dps > MAX_DPS) dps = MAX_DPS;
    int seq = in_sizes[0] / (dps * 1024);  // S element count = dps*seq*1024

    precompute_kernel<<<dps, 256>>>(R, WQ_w, WQ_b, WK_w, WK_b, WV_w, WV_b);

    constexpr int ROWS   = 64;
    constexpr int UNROLL = 4;
    int nblk = (seq + ROWS - 1) / ROWS;
    stream_kernel<ROWS, UNROLL><<<dim3(dps, nblk), 256>>>(S, S_mas, out, seq);
}